// round 1
// baseline (speedup 1.0000x reference)
#include <cuda_runtime.h>
#include <math.h>
#include <float.h>

// Problem constants
#define BATCH  2
#define NSEQ   2048
#define DIM    2048
#define NH     32
#define HD     64
#define QKVN   (3*DIM)          // 6144
#define NTOK   (BATCH*NSEQ)     // 4096
#define NBH    (BATCH*NH)       // 64
#define LN_EPS 1e-6f

// ---------------------------------------------------------------------------
// Scratch (device globals -- no runtime allocation allowed)
// ---------------------------------------------------------------------------
__device__ float g_qkv[(size_t)NTOK * QKVN];          // 100.7 MB
__device__ float g_q  [(size_t)NBH * NSEQ * HD];      // 33.6 MB
__device__ float g_k  [(size_t)NBH * NSEQ * HD];
__device__ float g_v  [(size_t)NBH * NSEQ * HD];
__device__ float g_ctx[(size_t)NTOK * DIM];           // 33.6 MB
__device__ int   g_mask_mode;                         // 0=u8, 1=i32, 2=f32

// ---------------------------------------------------------------------------
// Mask dtype detection (bool arrays may arrive as uint8 / int32 / float32)
// ---------------------------------------------------------------------------
__device__ __forceinline__ bool mask_at(const void* mp, int idx, int mode) {
    if (mode == 1) return ((const int*)mp)[idx] != 0;
    if (mode == 2) return ((const float*)mp)[idx] != 0.0f;
    return ((const unsigned char*)mp)[idx] != 0;
}

__global__ void detect_mask_kernel(const void* __restrict__ mp) {
    if (threadIdx.x != 0 || blockIdx.x != 0) return;
    // First 1024 int32 = 4096 bytes = size of a uint8 mask buffer (safe bound).
    const int* ip = (const int*)mp;
    bool iok = true;
    for (int i = 0; i < 1024; i++) {
        int v = ip[i];
        if (v != 0 && v != 1) { iok = false; break; }
    }
    if (iok) { g_mask_mode = 1; return; }
    const float* fp = (const float*)mp;
    bool fok = true;
    for (int i = 0; i < 1024; i++) {
        float v = fp[i];
        if (v != 0.0f && v != 1.0f) { fok = false; break; }
    }
    g_mask_mode = fok ? 2 : 0;
}

// ---------------------------------------------------------------------------
// NT GEMM: C[M,N] = A[M,K] * B[N,K]^T  (both row-major, K contiguous)
// 128x128 block tile, K-tile 8, 256 threads, 8x8 microtile (4+4 split).
// Requires M%128==0, N%128==0, K%8==0.
// ---------------------------------------------------------------------------
__global__ __launch_bounds__(256)
void gemm_nt(const float* __restrict__ A, const float* __restrict__ B,
             float* __restrict__ C, int M, int N, int K)
{
    __shared__ float As[8][128];
    __shared__ float Bs[8][128];

    const int tid  = threadIdx.x;
    const int lrow = tid >> 1;          // 0..127
    const int lcol = (tid & 1) * 4;     // 0 or 4
    const int tx   = tid & 15;
    const int ty   = tid >> 4;

    const float* Ap = A + (size_t)(blockIdx.y * 128 + lrow) * K + lcol;
    const float* Bp = B + (size_t)(blockIdx.x * 128 + lrow) * K + lcol;

    float acc[8][8];
#pragma unroll
    for (int i = 0; i < 8; i++)
#pragma unroll
        for (int j = 0; j < 8; j++) acc[i][j] = 0.0f;

    for (int k0 = 0; k0 < K; k0 += 8) {
        float4 av = *(const float4*)(Ap + k0);
        float4 bv = *(const float4*)(Bp + k0);
        As[lcol + 0][lrow] = av.x; As[lcol + 1][lrow] = av.y;
        As[lcol + 2][lrow] = av.z; As[lcol + 3][lrow] = av.w;
        Bs[lcol + 0][lrow] = bv.x; Bs[lcol + 1][lrow] = bv.y;
        Bs[lcol + 2][lrow] = bv.z; Bs[lcol + 3][lrow] = bv.w;
        __syncthreads();

#pragma unroll
        for (int kk = 0; kk < 8; kk++) {
            float4 a0 = *(const float4*)&As[kk][ty * 4];
            float4 a1 = *(const float4*)&As[kk][64 + ty * 4];
            float4 b0 = *(const float4*)&Bs[kk][tx * 4];
            float4 b1 = *(const float4*)&Bs[kk][64 + tx * 4];
            float ar[8] = {a0.x, a0.y, a0.z, a0.w, a1.x, a1.y, a1.z, a1.w};
            float br[8] = {b0.x, b0.y, b0.z, b0.w, b1.x, b1.y, b1.z, b1.w};
#pragma unroll
            for (int i = 0; i < 8; i++)
#pragma unroll
                for (int j = 0; j < 8; j++)
                    acc[i][j] += ar[i] * br[j];
        }
        __syncthreads();
    }

#pragma unroll
    for (int i = 0; i < 8; i++) {
        int r = blockIdx.y * 128 + (i < 4 ? ty * 4 + i : 64 + ty * 4 + (i - 4));
        float4 c0 = make_float4(acc[i][0], acc[i][1], acc[i][2], acc[i][3]);
        float4 c1 = make_float4(acc[i][4], acc[i][5], acc[i][6], acc[i][7]);
        float* Cr = C + (size_t)r * N + blockIdx.x * 128;
        *(float4*)(Cr + tx * 4)      = c0;
        *(float4*)(Cr + 64 + tx * 4) = c1;
    }
}

// ---------------------------------------------------------------------------
// LayerNorm (per head, D=64) + RoPE (rot_dim=32) + head-major relayout.
// One warp per (token, head); lane l owns dims l and l+32.
// ---------------------------------------------------------------------------
__global__ __launch_bounds__(128)
void lnrope_kernel(const float* __restrict__ qkv,
                   const float* __restrict__ qw, const float* __restrict__ qb,
                   const float* __restrict__ kw, const float* __restrict__ kb,
                   const float* __restrict__ freqs,
                   float* __restrict__ Q, float* __restrict__ K,
                   float* __restrict__ V)
{
    const int wid  = blockIdx.x * 4 + (threadIdx.x >> 5);
    const int lane = threadIdx.x & 31;
    const int token = wid >> 5;          // / NH
    const int h     = wid & 31;          // % NH
    const int b     = token / NSEQ;
    const int nn    = token % NSEQ;
    const int bh    = b * NH + h;

    const float* base = qkv + (size_t)token * QKVN + h * HD;
    float q1 = base[lane],            q2 = base[32 + lane];
    float k1 = base[DIM + lane],      k2 = base[DIM + 32 + lane];
    float v1 = base[2*DIM + lane],    v2 = base[2*DIM + 32 + lane];

    const float f  = freqs[nn * 32 + lane];
    const float cf = cosf(f), sf = sinf(f);

    float* qo = Q + ((size_t)bh * NSEQ + nn) * HD;
    float* ko = K + ((size_t)bh * NSEQ + nn) * HD;
    float* vo = V + ((size_t)bh * NSEQ + nn) * HD;

    // ---- q ----
    {
        float s = q1 + q2;
#pragma unroll
        for (int o = 16; o; o >>= 1) s += __shfl_xor_sync(0xffffffffu, s, o);
        float mean = s * (1.0f / HD);
        float d1 = q1 - mean, d2 = q2 - mean;
        float vs = d1 * d1 + d2 * d2;
#pragma unroll
        for (int o = 16; o; o >>= 1) vs += __shfl_xor_sync(0xffffffffu, vs, o);
        float inv = rsqrtf(vs * (1.0f / HD) + LN_EPS);
        float a = d1 * inv * qw[lane]      + qb[lane];
        float c = d2 * inv * qw[32 + lane] + qb[32 + lane];
        float p  = __shfl_xor_sync(0xffffffffu, a, 16);
        float rh = (lane < 16) ? -p : p;
        qo[lane]      = a * cf + rh * sf;
        qo[32 + lane] = c;
    }
    // ---- k ----
    {
        float s = k1 + k2;
#pragma unroll
        for (int o = 16; o; o >>= 1) s += __shfl_xor_sync(0xffffffffu, s, o);
        float mean = s * (1.0f / HD);
        float d1 = k1 - mean, d2 = k2 - mean;
        float vs = d1 * d1 + d2 * d2;
#pragma unroll
        for (int o = 16; o; o >>= 1) vs += __shfl_xor_sync(0xffffffffu, vs, o);
        float inv = rsqrtf(vs * (1.0f / HD) + LN_EPS);
        float a = d1 * inv * kw[lane]      + kb[lane];
        float c = d2 * inv * kw[32 + lane] + kb[32 + lane];
        float p  = __shfl_xor_sync(0xffffffffu, a, 16);
        float rh = (lane < 16) ? -p : p;
        ko[lane]      = a * cf + rh * sf;
        ko[32 + lane] = c;
    }
    // ---- v (copy) ----
    vo[lane]      = v1;
    vo[32 + lane] = v2;
}

// ---------------------------------------------------------------------------
// Flash-style causal+masked attention.
// Grid: (NSEQ/128, NBH). 128 threads, each owns one query row.
// 64-key SMEM tiles (K + V + mask). fp32 streaming softmax.
// ---------------------------------------------------------------------------
__global__ __launch_bounds__(128)
void attn_kernel(const float* __restrict__ Qg, const float* __restrict__ Kg,
                 const float* __restrict__ Vg, const void* __restrict__ maskp,
                 float* __restrict__ ctx)
{
    __shared__ float Ks[64][64];
    __shared__ float Vs[64][64];
    __shared__ float mk[64];

    const int tid = threadIdx.x;
    const int bh  = blockIdx.y;
    const int b   = bh / NH;
    const int h   = bh % NH;
    const int i   = blockIdx.x * 128 + tid;   // query row
    const int mode = g_mask_mode;
    const float scale = 0.125f;               // 1/sqrt(64)

    // q row into registers
    float4 qr[16];
    {
        const float* qp = Qg + ((size_t)bh * NSEQ + i) * HD;
#pragma unroll
        for (int d4 = 0; d4 < 16; d4++) qr[d4] = *(const float4*)(qp + d4 * 4);
    }

    float m = -FLT_MAX, l = 0.0f;
    float4 acc[16];
#pragma unroll
    for (int d4 = 0; d4 < 16; d4++) acc[d4] = make_float4(0.f, 0.f, 0.f, 0.f);

    const float* Kbase = Kg + (size_t)bh * NSEQ * HD;
    const float* Vbase = Vg + (size_t)bh * NSEQ * HD;
    const int jmax = blockIdx.x * 128 + 127;  // last causally-needed key

    for (int j0 = 0; j0 <= jmax; j0 += 64) {
        // cooperative tile load: 64x64 K and V (1024 float4 each, 8 per thread)
#pragma unroll
        for (int t = 0; t < 8; t++) {
            int lin = tid + t * 128;
            int r = lin >> 4, c4 = lin & 15;
            *(float4*)&Ks[r][c4 * 4] = *(const float4*)(Kbase + (size_t)(j0 + r) * HD + c4 * 4);
            *(float4*)&Vs[r][c4 * 4] = *(const float4*)(Vbase + (size_t)(j0 + r) * HD + c4 * 4);
        }
        if (tid < 64) mk[tid] = mask_at(maskp, b * NSEQ + j0 + tid, mode) ? 1.0f : 0.0f;
        __syncthreads();

        int jend = i - j0 + 1;
        if (jend > 64) jend = 64;
        for (int j = 0; j < jend; j++) {
            if (mk[j] == 0.0f) continue;
            float4 s4 = make_float4(0.f, 0.f, 0.f, 0.f);
#pragma unroll
            for (int d4 = 0; d4 < 16; d4++) {
                float4 kv = *(const float4*)&Ks[j][d4 * 4];
                s4.x += qr[d4].x * kv.x; s4.y += qr[d4].y * kv.y;
                s4.z += qr[d4].z * kv.z; s4.w += qr[d4].w * kv.w;
            }
            float s = (s4.x + s4.y + s4.z + s4.w) * scale;
            if (s > m) {
                float corr = __expf(m - s);   // 0 when m was -FLT_MAX
#pragma unroll
                for (int d4 = 0; d4 < 16; d4++) {
                    acc[d4].x *= corr; acc[d4].y *= corr;
                    acc[d4].z *= corr; acc[d4].w *= corr;
                }
                l *= corr;
                m = s;
            }
            float p = __expf(s - m);
            l += p;
#pragma unroll
            for (int d4 = 0; d4 < 16; d4++) {
                float4 vv = *(const float4*)&Vs[j][d4 * 4];
                acc[d4].x += p * vv.x; acc[d4].y += p * vv.y;
                acc[d4].z += p * vv.z; acc[d4].w += p * vv.w;
            }
        }
        __syncthreads();
    }

    // Edge case: no valid key => reference softmax is uniform over ALL 2048 keys.
    if (l == 0.0f) {
        for (int j = 0; j < NSEQ; j++) {
            const float* vp = Vbase + (size_t)j * HD;
#pragma unroll
            for (int d4 = 0; d4 < 16; d4++) {
                float4 vv = *(const float4*)(vp + d4 * 4);
                acc[d4].x += vv.x; acc[d4].y += vv.y;
                acc[d4].z += vv.z; acc[d4].w += vv.w;
            }
        }
        l = (float)NSEQ;
    }

    const float inv = 1.0f / l;
    float* outp = ctx + ((size_t)(b * NSEQ + i)) * DIM + h * HD;
#pragma unroll
    for (int d4 = 0; d4 < 16; d4++) {
        float4 o = make_float4(acc[d4].x * inv, acc[d4].y * inv,
                               acc[d4].z * inv, acc[d4].w * inv);
        *(float4*)(outp + d4 * 4) = o;
    }
}

// ---------------------------------------------------------------------------
// Zero masked output rows: out[b,n,:] = 0 where !mask[b,n]
// ---------------------------------------------------------------------------
__global__ void apply_mask_out(float* __restrict__ out, const void* __restrict__ maskp)
{
    const int mode = g_mask_mode;
    const int idx = blockIdx.x * blockDim.x + threadIdx.x;  // float4 index
    const int total4 = NTOK * (DIM / 4);
    if (idx >= total4) return;
    const int token = idx / (DIM / 4);
    if (!mask_at(maskp, token, mode)) {
        ((float4*)out)[idx] = make_float4(0.f, 0.f, 0.f, 0.f);
    }
}

// ---------------------------------------------------------------------------
// Launcher
// ---------------------------------------------------------------------------
extern "C" void kernel_launch(void* const* d_in, const int* in_sizes, int n_in,
                              void* d_out, int out_size)
{
    const float* x     = (const float*)d_in[0];
    const float* Wqkv  = (const float*)d_in[1];
    const float* Wout  = (const float*)d_in[2];
    const float* qlnw  = (const float*)d_in[3];
    const float* qlnb  = (const float*)d_in[4];
    const float* klnw  = (const float*)d_in[5];
    const float* klnb  = (const float*)d_in[6];
    const float* freqs = (const float*)d_in[7];
    const void*  mask  = d_in[8];
    float* out = (float*)d_out;

    float *qkv, *q, *k, *v, *ctx;
    cudaGetSymbolAddress((void**)&qkv, g_qkv);
    cudaGetSymbolAddress((void**)&q,   g_q);
    cudaGetSymbolAddress((void**)&k,   g_k);
    cudaGetSymbolAddress((void**)&v,   g_v);
    cudaGetSymbolAddress((void**)&ctx, g_ctx);

    detect_mask_kernel<<<1, 32>>>(mask);

    // qkv = x @ W_qkv^T : (4096 x 2048) * (6144 x 2048)^T
    gemm_nt<<<dim3(QKVN / 128, NTOK / 128), 256>>>(x, Wqkv, qkv, NTOK, QKVN, DIM);

    // per-head LN + RoPE + relayout to [b*h][n][d]
    lnrope_kernel<<<(NTOK * NH) / 4, 128>>>(qkv, qlnw, qlnb, klnw, klnb, freqs, q, k, v);

    // causal masked attention -> ctx[token][dim]
    attn_kernel<<<dim3(NSEQ / 128, NBH), 128>>>(q, k, v, mask, ctx);

    // out = ctx @ W_out^T : (4096 x 2048) * (2048 x 2048)^T
    gemm_nt<<<dim3(DIM / 128, NTOK / 128), 256>>>(ctx, Wout, out, NTOK, DIM, DIM);

    // zero masked rows
    apply_mask_out<<<(NTOK * (DIM / 4) + 255) / 256, 256>>>(out, mask);
}

// round 3
// speedup vs baseline: 1.7886x; 1.7886x over previous
#include <cuda_runtime.h>
#include <math.h>
#include <float.h>
#include <stdint.h>

// Problem constants
#define BATCH  2
#define NSEQ   2048
#define DIM    2048
#define NH     32
#define HD     64
#define QKVN   (3*DIM)          // 6144
#define NTOK   (BATCH*NSEQ)     // 4096
#define NBH    (BATCH*NH)       // 64
#define LN_EPS 1e-6f

// ---------------------------------------------------------------------------
// Scratch (device globals -- no runtime allocation allowed)
// ---------------------------------------------------------------------------
__device__ float g_qkv[(size_t)NTOK * QKVN];          // 100.7 MB
__device__ float g_q  [(size_t)NBH * NSEQ * HD];      // 33.6 MB
__device__ float g_k  [(size_t)NBH * NSEQ * HD];
__device__ float g_v  [(size_t)NBH * NSEQ * HD];
__device__ float g_ctx[(size_t)NTOK * DIM];           // 33.6 MB
__device__ int   g_mask_mode;                         // 0=u8, 1=i32, 2=f32

// ---------------------------------------------------------------------------
// Mask dtype detection
// ---------------------------------------------------------------------------
__device__ __forceinline__ bool mask_at(const void* mp, int idx, int mode) {
    if (mode == 1) return ((const int*)mp)[idx] != 0;
    if (mode == 2) return ((const float*)mp)[idx] != 0.0f;
    return ((const unsigned char*)mp)[idx] != 0;
}

__global__ void detect_mask_kernel(const void* __restrict__ mp) {
    if (threadIdx.x != 0 || blockIdx.x != 0) return;
    const int* ip = (const int*)mp;
    bool iok = true;
    for (int i = 0; i < 1024; i++) {
        int v = ip[i];
        if (v != 0 && v != 1) { iok = false; break; }
    }
    if (iok) { g_mask_mode = 1; return; }
    const float* fp = (const float*)mp;
    bool fok = true;
    for (int i = 0; i < 1024; i++) {
        float v = fp[i];
        if (v != 0.0f && v != 1.0f) { fok = false; break; }
    }
    g_mask_mode = fok ? 2 : 0;
}

// ---------------------------------------------------------------------------
// Tensor-core NT GEMM (tf32): C[M,N] = A[M,K] * B[N,K]^T, fp32 in/out.
// 128x128 block tile, K-tile 32, 256 thr (8 warps as 2x4), m16n8k8 frags,
// cp.async double-buffered smem. Requires M%128==0, N%128==0, K%32==0.
// ---------------------------------------------------------------------------
#define GK 32
#define SSTRIDE 36   // 32 + 4 pad -> conflict-free fragment LDS

__device__ __forceinline__ unsigned f2tf(float x) {
    unsigned u;
    asm("cvt.rna.tf32.f32 %0, %1;" : "=r"(u) : "f"(x));
    return u;
}

__device__ __forceinline__ void cpa16(void* sdst, const void* gsrc) {
    unsigned s = (unsigned)__cvta_generic_to_shared(sdst);
    asm volatile("cp.async.cg.shared.global [%0], [%1], 16;" :: "r"(s), "l"(gsrc));
}

__device__ __forceinline__ void mma_tf32(float* c, const unsigned* a, const unsigned* b) {
    asm volatile(
        "mma.sync.aligned.m16n8k8.row.col.f32.tf32.tf32.f32 "
        "{%0,%1,%2,%3},{%4,%5,%6,%7},{%8,%9},{%0,%1,%2,%3};"
        : "+f"(c[0]), "+f"(c[1]), "+f"(c[2]), "+f"(c[3])
        : "r"(a[0]), "r"(a[1]), "r"(a[2]), "r"(a[3]), "r"(b[0]), "r"(b[1]));
}

__global__ __launch_bounds__(256)
void gemm_nt_tf32(const float* __restrict__ A, const float* __restrict__ B,
                  float* __restrict__ C, int M, int N, int K)
{
    extern __shared__ float smem[];
    float (*As)[128][SSTRIDE] = (float(*)[128][SSTRIDE])smem;                 // [2][128][36]
    float (*Bs)[128][SSTRIDE] = (float(*)[128][SSTRIDE])(smem + 2*128*SSTRIDE);

    const int tid  = threadIdx.x;
    const int wid  = tid >> 5;
    const int lane = tid & 31;
    const int wm   = wid >> 2;          // 0..1 : 64 rows each
    const int wn   = wid & 3;           // 0..3 : 32 cols each
    const int g    = lane >> 2;         // 0..7
    const int tg   = lane & 3;          // 0..3

    // cp.async loader mapping: 32 rows/pass x 4 passes, 8 threads x 16B per row
    const int ldRow = tid >> 3;         // 0..31
    const int ldCol = (tid & 7) * 4;    // float offset 0..28

    const float* Ag = A + (size_t)(blockIdx.y * 128 + ldRow) * K + ldCol;
    const float* Bg = B + (size_t)(blockIdx.x * 128 + ldRow) * K + ldCol;
    const size_t r32 = (size_t)32 * K;

    float acc[4][4][4];
#pragma unroll
    for (int i = 0; i < 4; i++)
#pragma unroll
        for (int j = 0; j < 4; j++)
#pragma unroll
            for (int c = 0; c < 4; c++) acc[i][j][c] = 0.0f;

    // prologue: stage 0
#pragma unroll
    for (int p = 0; p < 4; p++) {
        cpa16(&As[0][ldRow + 32*p][ldCol], Ag + (size_t)p * r32);
        cpa16(&Bs[0][ldRow + 32*p][ldCol], Bg + (size_t)p * r32);
    }
    asm volatile("cp.async.commit_group;");

    const int KT = K / GK;
    for (int kt = 0; kt < KT; kt++) {
        const int s = kt & 1;
        if (kt + 1 < KT) {
            const int kb = (kt + 1) * GK;
#pragma unroll
            for (int p = 0; p < 4; p++) {
                cpa16(&As[s ^ 1][ldRow + 32*p][ldCol], Ag + (size_t)p * r32 + kb);
                cpa16(&Bs[s ^ 1][ldRow + 32*p][ldCol], Bg + (size_t)p * r32 + kb);
            }
            asm volatile("cp.async.commit_group;");
            asm volatile("cp.async.wait_group 1;");
        } else {
            asm volatile("cp.async.wait_group 0;");
        }
        __syncthreads();

#pragma unroll
        for (int ks = 0; ks < 4; ks++) {
            const int k0 = ks * 8;
            unsigned a[4][4];
#pragma unroll
            for (int mf = 0; mf < 4; mf++) {
                const int r = wm * 64 + mf * 16 + g;
                a[mf][0] = f2tf(As[s][r    ][k0 + tg]);
                a[mf][1] = f2tf(As[s][r + 8][k0 + tg]);
                a[mf][2] = f2tf(As[s][r    ][k0 + tg + 4]);
                a[mf][3] = f2tf(As[s][r + 8][k0 + tg + 4]);
            }
            unsigned b[4][2];
#pragma unroll
            for (int nf = 0; nf < 4; nf++) {
                const int c = wn * 32 + nf * 8 + g;
                b[nf][0] = f2tf(Bs[s][c][k0 + tg]);
                b[nf][1] = f2tf(Bs[s][c][k0 + tg + 4]);
            }
#pragma unroll
            for (int mf = 0; mf < 4; mf++)
#pragma unroll
                for (int nf = 0; nf < 4; nf++)
                    mma_tf32(acc[mf][nf], a[mf], b[nf]);
        }
        __syncthreads();
    }

    // epilogue
#pragma unroll
    for (int mf = 0; mf < 4; mf++) {
        const int r0 = blockIdx.y * 128 + wm * 64 + mf * 16 + g;
#pragma unroll
        for (int nf = 0; nf < 4; nf++) {
            const int c0 = blockIdx.x * 128 + wn * 32 + nf * 8 + tg * 2;
            float2 lo = make_float2(acc[mf][nf][0], acc[mf][nf][1]);
            float2 hi = make_float2(acc[mf][nf][2], acc[mf][nf][3]);
            *(float2*)(C + (size_t)r0 * N + c0)       = lo;
            *(float2*)(C + (size_t)(r0 + 8) * N + c0) = hi;
        }
    }
}

// ---------------------------------------------------------------------------
// LayerNorm (per head, D=64) + RoPE (rot_dim=32) + head-major relayout.
// ---------------------------------------------------------------------------
__global__ __launch_bounds__(128)
void lnrope_kernel(const float* __restrict__ qkv,
                   const float* __restrict__ qw, const float* __restrict__ qb,
                   const float* __restrict__ kw, const float* __restrict__ kb,
                   const float* __restrict__ freqs,
                   float* __restrict__ Q, float* __restrict__ K,
                   float* __restrict__ V)
{
    const int wid  = blockIdx.x * 4 + (threadIdx.x >> 5);
    const int lane = threadIdx.x & 31;
    const int token = wid >> 5;
    const int h     = wid & 31;
    const int b     = token / NSEQ;
    const int nn    = token % NSEQ;
    const int bh    = b * NH + h;

    const float* base = qkv + (size_t)token * QKVN + h * HD;
    float q1 = base[lane],            q2 = base[32 + lane];
    float k1 = base[DIM + lane],      k2 = base[DIM + 32 + lane];
    float v1 = base[2*DIM + lane],    v2 = base[2*DIM + 32 + lane];

    const float f  = freqs[nn * 32 + lane];
    const float cf = cosf(f), sf = sinf(f);

    float* qo = Q + ((size_t)bh * NSEQ + nn) * HD;
    float* ko = K + ((size_t)bh * NSEQ + nn) * HD;
    float* vo = V + ((size_t)bh * NSEQ + nn) * HD;

    {
        float s = q1 + q2;
#pragma unroll
        for (int o = 16; o; o >>= 1) s += __shfl_xor_sync(0xffffffffu, s, o);
        float mean = s * (1.0f / HD);
        float d1 = q1 - mean, d2 = q2 - mean;
        float vs = d1 * d1 + d2 * d2;
#pragma unroll
        for (int o = 16; o; o >>= 1) vs += __shfl_xor_sync(0xffffffffu, vs, o);
        float inv = rsqrtf(vs * (1.0f / HD) + LN_EPS);
        float a = d1 * inv * qw[lane]      + qb[lane];
        float c = d2 * inv * qw[32 + lane] + qb[32 + lane];
        float p  = __shfl_xor_sync(0xffffffffu, a, 16);
        float rh = (lane < 16) ? -p : p;
        qo[lane]      = a * cf + rh * sf;
        qo[32 + lane] = c;
    }
    {
        float s = k1 + k2;
#pragma unroll
        for (int o = 16; o; o >>= 1) s += __shfl_xor_sync(0xffffffffu, s, o);
        float mean = s * (1.0f / HD);
        float d1 = k1 - mean, d2 = k2 - mean;
        float vs = d1 * d1 + d2 * d2;
#pragma unroll
        for (int o = 16; o; o >>= 1) vs += __shfl_xor_sync(0xffffffffu, vs, o);
        float inv = rsqrtf(vs * (1.0f / HD) + LN_EPS);
        float a = d1 * inv * kw[lane]      + kb[lane];
        float c = d2 * inv * kw[32 + lane] + kb[32 + lane];
        float p  = __shfl_xor_sync(0xffffffffu, a, 16);
        float rh = (lane < 16) ? -p : p;
        ko[lane]      = a * cf + rh * sf;
        ko[32 + lane] = c;
    }
    vo[lane]      = v1;
    vo[32 + lane] = v2;
}

// ---------------------------------------------------------------------------
// Flash-style causal+masked attention (fp32).
// ---------------------------------------------------------------------------
__global__ __launch_bounds__(128)
void attn_kernel(const float* __restrict__ Qg, const float* __restrict__ Kg,
                 const float* __restrict__ Vg, const void* __restrict__ maskp,
                 float* __restrict__ ctx)
{
    __shared__ float Ks[64][64];
    __shared__ float Vs[64][64];
    __shared__ float mk[64];

    const int tid = threadIdx.x;
    const int bh  = blockIdx.y;
    const int b   = bh / NH;
    const int h   = bh % NH;
    const int i   = blockIdx.x * 128 + tid;
    const int mode = g_mask_mode;
    const float scale = 0.125f;

    float4 qr[16];
    {
        const float* qp = Qg + ((size_t)bh * NSEQ + i) * HD;
#pragma unroll
        for (int d4 = 0; d4 < 16; d4++) qr[d4] = *(const float4*)(qp + d4 * 4);
    }

    float m = -FLT_MAX, l = 0.0f;
    float4 acc[16];
#pragma unroll
    for (int d4 = 0; d4 < 16; d4++) acc[d4] = make_float4(0.f, 0.f, 0.f, 0.f);

    const float* Kbase = Kg + (size_t)bh * NSEQ * HD;
    const float* Vbase = Vg + (size_t)bh * NSEQ * HD;
    const int jmax = blockIdx.x * 128 + 127;

    for (int j0 = 0; j0 <= jmax; j0 += 64) {
#pragma unroll
        for (int t = 0; t < 8; t++) {
            int lin = tid + t * 128;
            int r = lin >> 4, c4 = lin & 15;
            *(float4*)&Ks[r][c4 * 4] = *(const float4*)(Kbase + (size_t)(j0 + r) * HD + c4 * 4);
            *(float4*)&Vs[r][c4 * 4] = *(const float4*)(Vbase + (size_t)(j0 + r) * HD + c4 * 4);
        }
        if (tid < 64) mk[tid] = mask_at(maskp, b * NSEQ + j0 + tid, mode) ? 1.0f : 0.0f;
        __syncthreads();

        int jend = i - j0 + 1;
        if (jend > 64) jend = 64;
        for (int j = 0; j < jend; j++) {
            if (mk[j] == 0.0f) continue;
            float4 s4 = make_float4(0.f, 0.f, 0.f, 0.f);
#pragma unroll
            for (int d4 = 0; d4 < 16; d4++) {
                float4 kv = *(const float4*)&Ks[j][d4 * 4];
                s4.x += qr[d4].x * kv.x; s4.y += qr[d4].y * kv.y;
                s4.z += qr[d4].z * kv.z; s4.w += qr[d4].w * kv.w;
            }
            float s = (s4.x + s4.y + s4.z + s4.w) * scale;
            if (s > m) {
                float corr = __expf(m - s);
#pragma unroll
                for (int d4 = 0; d4 < 16; d4++) {
                    acc[d4].x *= corr; acc[d4].y *= corr;
                    acc[d4].z *= corr; acc[d4].w *= corr;
                }
                l *= corr;
                m = s;
            }
            float p = __expf(s - m);
            l += p;
#pragma unroll
            for (int d4 = 0; d4 < 16; d4++) {
                float4 vv = *(const float4*)&Vs[j][d4 * 4];
                acc[d4].x += p * vv.x; acc[d4].y += p * vv.y;
                acc[d4].z += p * vv.z; acc[d4].w += p * vv.w;
            }
        }
        __syncthreads();
    }

    if (l == 0.0f) {
        for (int j = 0; j < NSEQ; j++) {
            const float* vp = Vbase + (size_t)j * HD;
#pragma unroll
            for (int d4 = 0; d4 < 16; d4++) {
                float4 vv = *(const float4*)(vp + d4 * 4);
                acc[d4].x += vv.x; acc[d4].y += vv.y;
                acc[d4].z += vv.z; acc[d4].w += vv.w;
            }
        }
        l = (float)NSEQ;
    }

    const float inv = 1.0f / l;
    float* outp = ctx + ((size_t)(b * NSEQ + i)) * DIM + h * HD;
#pragma unroll
    for (int d4 = 0; d4 < 16; d4++) {
        float4 o = make_float4(acc[d4].x * inv, acc[d4].y * inv,
                               acc[d4].z * inv, acc[d4].w * inv);
        *(float4*)(outp + d4 * 4) = o;
    }
}

// ---------------------------------------------------------------------------
// Zero masked output rows
// ---------------------------------------------------------------------------
__global__ void apply_mask_out(float* __restrict__ out, const void* __restrict__ maskp)
{
    const int mode = g_mask_mode;
    const int idx = blockIdx.x * blockDim.x + threadIdx.x;
    const int total4 = NTOK * (DIM / 4);
    if (idx >= total4) return;
    const int token = idx / (DIM / 4);
    if (!mask_at(maskp, token, mode)) {
        ((float4*)out)[idx] = make_float4(0.f, 0.f, 0.f, 0.f);
    }
}

// ---------------------------------------------------------------------------
// Launcher
// ---------------------------------------------------------------------------
extern "C" void kernel_launch(void* const* d_in, const int* in_sizes, int n_in,
                              void* d_out, int out_size)
{
    const float* x     = (const float*)d_in[0];
    const float* Wqkv  = (const float*)d_in[1];
    const float* Wout  = (const float*)d_in[2];
    const float* qlnw  = (const float*)d_in[3];
    const float* qlnb  = (const float*)d_in[4];
    const float* klnw  = (const float*)d_in[5];
    const float* klnb  = (const float*)d_in[6];
    const float* freqs = (const float*)d_in[7];
    const void*  mask  = d_in[8];
    float* out = (float*)d_out;

    float *qkv, *q, *k, *v, *ctx;
    cudaGetSymbolAddress((void**)&qkv, g_qkv);
    cudaGetSymbolAddress((void**)&q,   g_q);
    cudaGetSymbolAddress((void**)&k,   g_k);
    cudaGetSymbolAddress((void**)&v,   g_v);
    cudaGetSymbolAddress((void**)&ctx, g_ctx);

    const int smem_bytes = 4 * 128 * SSTRIDE * (int)sizeof(float);  // 73728
    cudaFuncSetAttribute(gemm_nt_tf32, cudaFuncAttributeMaxDynamicSharedMemorySize, smem_bytes);

    detect_mask_kernel<<<1, 32>>>(mask);

    // qkv = x @ W_qkv^T
    gemm_nt_tf32<<<dim3(QKVN / 128, NTOK / 128), 256, smem_bytes>>>(x, Wqkv, qkv, NTOK, QKVN, DIM);

    // per-head LN + RoPE + relayout
    lnrope_kernel<<<(NTOK * NH) / 4, 128>>>(qkv, qlnw, qlnb, klnw, klnb, freqs, q, k, v);

    // attention
    attn_kernel<<<dim3(NSEQ / 128, NBH), 128>>>(q, k, v, mask, ctx);

    // out = ctx @ W_out^T
    gemm_nt_tf32<<<dim3(DIM / 128, NTOK / 128), 256, smem_bytes>>>(ctx, Wout, out, NTOK, DIM, DIM);

    // zero masked rows
    apply_mask_out<<<(NTOK * (DIM / 4) + 255) / 256, 256>>>(out, mask);
}

// round 5
// speedup vs baseline: 3.6279x; 2.0283x over previous
#include <cuda_runtime.h>
#include <math.h>
#include <float.h>
#include <stdint.h>

// Problem constants
#define BATCH  2
#define NSEQ   2048
#define DIM    2048
#define NH     32
#define HD     64
#define QKVN   (3*DIM)          // 6144
#define NTOK   (BATCH*NSEQ)     // 4096
#define NBH    (BATCH*NH)       // 64
#define LN_EPS 1e-6f

// ---------------------------------------------------------------------------
// Scratch (device globals -- no runtime allocation allowed)
// ---------------------------------------------------------------------------
__device__ float g_qkv[(size_t)NTOK * QKVN];          // 100.7 MB
__device__ float g_q  [(size_t)NBH * NSEQ * HD];      // 33.6 MB
__device__ float g_k  [(size_t)NBH * NSEQ * HD];
__device__ float g_v  [(size_t)NBH * NSEQ * HD];
__device__ float g_ctx[(size_t)NTOK * DIM];           // 33.6 MB
__device__ int   g_mask_mode;                         // 0=u8, 1=i32, 2=f32

// ---------------------------------------------------------------------------
// Mask dtype detection
// ---------------------------------------------------------------------------
__device__ __forceinline__ bool mask_at(const void* mp, int idx, int mode) {
    if (mode == 1) return ((const int*)mp)[idx] != 0;
    if (mode == 2) return ((const float*)mp)[idx] != 0.0f;
    return ((const unsigned char*)mp)[idx] != 0;
}

__global__ void detect_mask_kernel(const void* __restrict__ mp) {
    if (threadIdx.x != 0 || blockIdx.x != 0) return;
    const int* ip = (const int*)mp;
    bool iok = true;
    for (int i = 0; i < 1024; i++) {
        int v = ip[i];
        if (v != 0 && v != 1) { iok = false; break; }
    }
    if (iok) { g_mask_mode = 1; return; }
    const float* fp = (const float*)mp;
    bool fok = true;
    for (int i = 0; i < 1024; i++) {
        float v = fp[i];
        if (v != 0.0f && v != 1.0f) { fok = false; break; }
    }
    g_mask_mode = fok ? 2 : 0;
}

// ---------------------------------------------------------------------------
// tf32 MMA primitives (shared by GEMM and attention)
// ---------------------------------------------------------------------------
__device__ __forceinline__ unsigned f2tf(float x) {
    unsigned u;
    asm("cvt.rna.tf32.f32 %0, %1;" : "=r"(u) : "f"(x));
    return u;
}

__device__ __forceinline__ void cpa16(void* sdst, const void* gsrc) {
    unsigned s = (unsigned)__cvta_generic_to_shared(sdst);
    asm volatile("cp.async.cg.shared.global [%0], [%1], 16;" :: "r"(s), "l"(gsrc));
}

__device__ __forceinline__ void mma_tf32(float* c, const unsigned* a, const unsigned* b) {
    asm volatile(
        "mma.sync.aligned.m16n8k8.row.col.f32.tf32.tf32.f32 "
        "{%0,%1,%2,%3},{%4,%5,%6,%7},{%8,%9},{%0,%1,%2,%3};"
        : "+f"(c[0]), "+f"(c[1]), "+f"(c[2]), "+f"(c[3])
        : "r"(a[0]), "r"(a[1]), "r"(a[2]), "r"(a[3]), "r"(b[0]), "r"(b[1]));
}

// ---------------------------------------------------------------------------
// Tensor-core NT GEMM (tf32): C[M,N] = A[M,K] * B[N,K]^T, fp32 in/out.
// ---------------------------------------------------------------------------
#define GK 32
#define SSTRIDE 36

__global__ __launch_bounds__(256)
void gemm_nt_tf32(const float* __restrict__ A, const float* __restrict__ B,
                  float* __restrict__ C, int M, int N, int K)
{
    extern __shared__ float smem[];
    float (*As)[128][SSTRIDE] = (float(*)[128][SSTRIDE])smem;
    float (*Bs)[128][SSTRIDE] = (float(*)[128][SSTRIDE])(smem + 2*128*SSTRIDE);

    const int tid  = threadIdx.x;
    const int wid  = tid >> 5;
    const int lane = tid & 31;
    const int wm   = wid >> 2;
    const int wn   = wid & 3;
    const int g    = lane >> 2;
    const int tg   = lane & 3;

    const int ldRow = tid >> 3;
    const int ldCol = (tid & 7) * 4;

    const float* Ag = A + (size_t)(blockIdx.y * 128 + ldRow) * K + ldCol;
    const float* Bg = B + (size_t)(blockIdx.x * 128 + ldRow) * K + ldCol;
    const size_t r32 = (size_t)32 * K;

    float acc[4][4][4];
#pragma unroll
    for (int i = 0; i < 4; i++)
#pragma unroll
        for (int j = 0; j < 4; j++)
#pragma unroll
            for (int c = 0; c < 4; c++) acc[i][j][c] = 0.0f;

#pragma unroll
    for (int p = 0; p < 4; p++) {
        cpa16(&As[0][ldRow + 32*p][ldCol], Ag + (size_t)p * r32);
        cpa16(&Bs[0][ldRow + 32*p][ldCol], Bg + (size_t)p * r32);
    }
    asm volatile("cp.async.commit_group;");

    const int KT = K / GK;
    for (int kt = 0; kt < KT; kt++) {
        const int s = kt & 1;
        if (kt + 1 < KT) {
            const int kb = (kt + 1) * GK;
#pragma unroll
            for (int p = 0; p < 4; p++) {
                cpa16(&As[s ^ 1][ldRow + 32*p][ldCol], Ag + (size_t)p * r32 + kb);
                cpa16(&Bs[s ^ 1][ldRow + 32*p][ldCol], Bg + (size_t)p * r32 + kb);
            }
            asm volatile("cp.async.commit_group;");
            asm volatile("cp.async.wait_group 1;");
        } else {
            asm volatile("cp.async.wait_group 0;");
        }
        __syncthreads();

#pragma unroll
        for (int ks = 0; ks < 4; ks++) {
            const int k0 = ks * 8;
            unsigned a[4][4];
#pragma unroll
            for (int mf = 0; mf < 4; mf++) {
                const int r = wm * 64 + mf * 16 + g;
                a[mf][0] = f2tf(As[s][r    ][k0 + tg]);
                a[mf][1] = f2tf(As[s][r + 8][k0 + tg]);
                a[mf][2] = f2tf(As[s][r    ][k0 + tg + 4]);
                a[mf][3] = f2tf(As[s][r + 8][k0 + tg + 4]);
            }
            unsigned b[4][2];
#pragma unroll
            for (int nf = 0; nf < 4; nf++) {
                const int c = wn * 32 + nf * 8 + g;
                b[nf][0] = f2tf(Bs[s][c][k0 + tg]);
                b[nf][1] = f2tf(Bs[s][c][k0 + tg + 4]);
            }
#pragma unroll
            for (int mf = 0; mf < 4; mf++)
#pragma unroll
                for (int nf = 0; nf < 4; nf++)
                    mma_tf32(acc[mf][nf], a[mf], b[nf]);
        }
        __syncthreads();
    }

#pragma unroll
    for (int mf = 0; mf < 4; mf++) {
        const int r0 = blockIdx.y * 128 + wm * 64 + mf * 16 + g;
#pragma unroll
        for (int nf = 0; nf < 4; nf++) {
            const int c0 = blockIdx.x * 128 + wn * 32 + nf * 8 + tg * 2;
            float2 lo = make_float2(acc[mf][nf][0], acc[mf][nf][1]);
            float2 hi = make_float2(acc[mf][nf][2], acc[mf][nf][3]);
            *(float2*)(C + (size_t)r0 * N + c0)       = lo;
            *(float2*)(C + (size_t)(r0 + 8) * N + c0) = hi;
        }
    }
}

// ---------------------------------------------------------------------------
// LayerNorm (per head, D=64) + RoPE (rot_dim=32) + head-major relayout.
// ---------------------------------------------------------------------------
__global__ __launch_bounds__(128)
void lnrope_kernel(const float* __restrict__ qkv,
                   const float* __restrict__ qw, const float* __restrict__ qb,
                   const float* __restrict__ kw, const float* __restrict__ kb,
                   const float* __restrict__ freqs,
                   float* __restrict__ Q, float* __restrict__ K,
                   float* __restrict__ V)
{
    const int wid  = blockIdx.x * 4 + (threadIdx.x >> 5);
    const int lane = threadIdx.x & 31;
    const int token = wid >> 5;
    const int h     = wid & 31;
    const int b     = token / NSEQ;
    const int nn    = token % NSEQ;
    const int bh    = b * NH + h;

    const float* base = qkv + (size_t)token * QKVN + h * HD;
    float q1 = base[lane],            q2 = base[32 + lane];
    float k1 = base[DIM + lane],      k2 = base[DIM + 32 + lane];
    float v1 = base[2*DIM + lane],    v2 = base[2*DIM + 32 + lane];

    const float f  = freqs[nn * 32 + lane];
    const float cf = cosf(f), sf = sinf(f);

    float* qo = Q + ((size_t)bh * NSEQ + nn) * HD;
    float* ko = K + ((size_t)bh * NSEQ + nn) * HD;
    float* vo = V + ((size_t)bh * NSEQ + nn) * HD;

    {
        float s = q1 + q2;
#pragma unroll
        for (int o = 16; o; o >>= 1) s += __shfl_xor_sync(0xffffffffu, s, o);
        float mean = s * (1.0f / HD);
        float d1 = q1 - mean, d2 = q2 - mean;
        float vs = d1 * d1 + d2 * d2;
#pragma unroll
        for (int o = 16; o; o >>= 1) vs += __shfl_xor_sync(0xffffffffu, vs, o);
        float inv = rsqrtf(vs * (1.0f / HD) + LN_EPS);
        float a = d1 * inv * qw[lane]      + qb[lane];
        float c = d2 * inv * qw[32 + lane] + qb[32 + lane];
        float p  = __shfl_xor_sync(0xffffffffu, a, 16);
        float rh = (lane < 16) ? -p : p;
        qo[lane]      = a * cf + rh * sf;
        qo[32 + lane] = c;
    }
    {
        float s = k1 + k2;
#pragma unroll
        for (int o = 16; o; o >>= 1) s += __shfl_xor_sync(0xffffffffu, s, o);
        float mean = s * (1.0f / HD);
        float d1 = k1 - mean, d2 = k2 - mean;
        float vs = d1 * d1 + d2 * d2;
#pragma unroll
        for (int o = 16; o; o >>= 1) vs += __shfl_xor_sync(0xffffffffu, vs, o);
        float inv = rsqrtf(vs * (1.0f / HD) + LN_EPS);
        float a = d1 * inv * kw[lane]      + kb[lane];
        float c = d2 * inv * kw[32 + lane] + kb[32 + lane];
        float p  = __shfl_xor_sync(0xffffffffu, a, 16);
        float rh = (lane < 16) ? -p : p;
        ko[lane]      = a * cf + rh * sf;
        ko[32 + lane] = c;
    }
    vo[lane]      = v1;
    vo[32 + lane] = v2;
}

// ---------------------------------------------------------------------------
// Tensor-core flash attention (tf32 MMA, fp32 softmax).
// Block = 128 query rows x 1 head. 4 warps, each owns 32 rows (2 m16 frags).
// Key tiles of 64 in smem (stride 68 floats -> conflict-free frag LDS).
// P staged through warp-private smem rows.
// ---------------------------------------------------------------------------
#define KST 68

__global__ __launch_bounds__(128, 1)
void attn_tc_kernel(const float* __restrict__ Qg, const float* __restrict__ Kg,
                    const float* __restrict__ Vg, const void* __restrict__ maskp,
                    float* __restrict__ ctx)
{
    extern __shared__ float sm[];
    float* Ks = sm;                        // [64][KST]
    float* Vs = sm + 64*KST;               // [64][KST]
    float* Ps = sm + 2*64*KST;             // [128][KST] (also Q staging)
    float* mk = sm + 2*64*KST + 128*KST;   // [64]

    const int tid  = threadIdx.x;
    const int wid  = tid >> 5;
    const int lane = tid & 31;
    const int g    = lane >> 2;
    const int tg   = lane & 3;
    const int rbase = wid * 32;

    const int bh   = blockIdx.y;
    const int b    = bh >> 5;
    const int head = bh & 31;
    const int qbase = blockIdx.x * 128;
    const int mode = g_mask_mode;
    const float scale = 0.125f;

    const float* Kbase = Kg + (size_t)bh * NSEQ * HD;
    const float* Vbase = Vg + (size_t)bh * NSEQ * HD;

    // ---- stage Q tile into Ps, extract A-fragments to registers ----
    {
        const float* Qrow = Qg + ((size_t)bh * NSEQ + qbase) * HD;
#pragma unroll
        for (int t = 0; t < 16; t++) {
            int lin = tid + t * 128;
            int r = lin >> 4, c4 = lin & 15;
            *(float4*)&Ps[r * KST + c4 * 4] = *(const float4*)(Qrow + (size_t)r * HD + c4 * 4);
        }
    }
    __syncthreads();

    unsigned qf[2][8][4];
#pragma unroll
    for (int mf = 0; mf < 2; mf++) {
        const int r0 = rbase + mf * 16 + g;
#pragma unroll
        for (int ks = 0; ks < 8; ks++) {
            const int k0 = ks * 8;
            qf[mf][ks][0] = f2tf(Ps[r0 * KST + k0 + tg]);
            qf[mf][ks][1] = f2tf(Ps[(r0 + 8) * KST + k0 + tg]);
            qf[mf][ks][2] = f2tf(Ps[r0 * KST + k0 + tg + 4]);
            qf[mf][ks][3] = f2tf(Ps[(r0 + 8) * KST + k0 + tg + 4]);
        }
    }
    __syncthreads();

    float o[2][8][4];
#pragma unroll
    for (int mf = 0; mf < 2; mf++)
#pragma unroll
        for (int nf = 0; nf < 8; nf++)
#pragma unroll
            for (int c = 0; c < 4; c++) o[mf][nf][c] = 0.0f;

    float mrow[2][2] = {{-FLT_MAX, -FLT_MAX}, {-FLT_MAX, -FLT_MAX}};
    float lrow[2][2] = {{0.0f, 0.0f}, {0.0f, 0.0f}};

    const int jmax = qbase + 127;
    for (int j0 = 0; j0 <= jmax; j0 += 64) {
        // ---- load K/V tiles + mask ----
#pragma unroll
        for (int t = 0; t < 8; t++) {
            int lin = tid + t * 128;
            int r = lin >> 4, c4 = lin & 15;
            *(float4*)&Ks[r * KST + c4 * 4] = *(const float4*)(Kbase + (size_t)(j0 + r) * HD + c4 * 4);
            *(float4*)&Vs[r * KST + c4 * 4] = *(const float4*)(Vbase + (size_t)(j0 + r) * HD + c4 * 4);
        }
        if (tid < 64) mk[tid] = mask_at(maskp, b * NSEQ + j0 + tid, mode) ? 1.0f : 0.0f;
        __syncthreads();

        // ---- S = Q K^T ----
        float s[2][8][4];
#pragma unroll
        for (int mf = 0; mf < 2; mf++)
#pragma unroll
            for (int nf = 0; nf < 8; nf++)
#pragma unroll
                for (int c = 0; c < 4; c++) s[mf][nf][c] = 0.0f;

#pragma unroll
        for (int ks = 0; ks < 8; ks++) {
            const int k0 = ks * 8;
            unsigned bfr[8][2];
#pragma unroll
            for (int nf = 0; nf < 8; nf++) {
                const int c = nf * 8 + g;
                bfr[nf][0] = f2tf(Ks[c * KST + k0 + tg]);
                bfr[nf][1] = f2tf(Ks[c * KST + k0 + tg + 4]);
            }
#pragma unroll
            for (int mf = 0; mf < 2; mf++)
#pragma unroll
                for (int nf = 0; nf < 8; nf++)
                    mma_tf32(s[mf][nf], qf[mf][ks], bfr[nf]);
        }

        // ---- scale + key-mask + causal ----
#pragma unroll
        for (int mf = 0; mf < 2; mf++) {
            const int i0 = qbase + rbase + mf * 16 + g;
#pragma unroll
            for (int nf = 0; nf < 8; nf++) {
                const int jl = nf * 8 + 2 * tg;
                const int jg = j0 + jl;
                const float m0 = mk[jl], m1 = mk[jl + 1];
                s[mf][nf][0] = (m0 != 0.0f && jg     <= i0    ) ? s[mf][nf][0] * scale : -FLT_MAX;
                s[mf][nf][1] = (m1 != 0.0f && jg + 1 <= i0    ) ? s[mf][nf][1] * scale : -FLT_MAX;
                s[mf][nf][2] = (m0 != 0.0f && jg     <= i0 + 8) ? s[mf][nf][2] * scale : -FLT_MAX;
                s[mf][nf][3] = (m1 != 0.0f && jg + 1 <= i0 + 8) ? s[mf][nf][3] * scale : -FLT_MAX;
            }
        }

        // ---- streaming softmax, write P to warp-private smem rows ----
#pragma unroll
        for (int mf = 0; mf < 2; mf++) {
#pragma unroll
            for (int h = 0; h < 2; h++) {
                float rm = -FLT_MAX;
#pragma unroll
                for (int nf = 0; nf < 8; nf++)
                    rm = fmaxf(rm, fmaxf(s[mf][nf][h*2], s[mf][nf][h*2+1]));
                rm = fmaxf(rm, __shfl_xor_sync(0xffffffffu, rm, 1));
                rm = fmaxf(rm, __shfl_xor_sync(0xffffffffu, rm, 2));

                const float mo = mrow[mf][h];
                const float mn = fmaxf(mo, rm);
                const float corr = __expf(mo - mn);
                mrow[mf][h] = mn;
                float lr = lrow[mf][h] * corr;
#pragma unroll
                for (int nf = 0; nf < 8; nf++) {
                    o[mf][nf][h*2]   *= corr;
                    o[mf][nf][h*2+1] *= corr;
                }
                const int r = rbase + mf * 16 + g + h * 8;
#pragma unroll
                for (int nf = 0; nf < 8; nf++) {
                    float sv0 = s[mf][nf][h*2];
                    float sv1 = s[mf][nf][h*2+1];
                    float p0 = (sv0 < -1e37f) ? 0.0f : __expf(sv0 - mn);
                    float p1 = (sv1 < -1e37f) ? 0.0f : __expf(sv1 - mn);
                    lr += p0 + p1;
                    *(float2*)&Ps[r * KST + nf * 8 + 2 * tg] = make_float2(p0, p1);
                }
                lrow[mf][h] = lr;
            }
        }
        __syncwarp();

        // ---- O += P V ----
#pragma unroll
        for (int ks = 0; ks < 8; ks++) {
            const int k0 = ks * 8;
            unsigned af[2][4];
#pragma unroll
            for (int mf = 0; mf < 2; mf++) {
                const int r0 = rbase + mf * 16 + g;
                af[mf][0] = f2tf(Ps[r0 * KST + k0 + tg]);
                af[mf][1] = f2tf(Ps[(r0 + 8) * KST + k0 + tg]);
                af[mf][2] = f2tf(Ps[r0 * KST + k0 + tg + 4]);
                af[mf][3] = f2tf(Ps[(r0 + 8) * KST + k0 + tg + 4]);
            }
            unsigned bfr[8][2];
#pragma unroll
            for (int nf = 0; nf < 8; nf++) {
                const int d = nf * 8 + g;
                bfr[nf][0] = f2tf(Vs[(k0 + tg) * KST + d]);
                bfr[nf][1] = f2tf(Vs[(k0 + tg + 4) * KST + d]);
            }
#pragma unroll
            for (int mf = 0; mf < 2; mf++)
#pragma unroll
                for (int nf = 0; nf < 8; nf++)
                    mma_tf32(o[mf][nf], af[mf], bfr[nf]);
        }
        __syncthreads();
    }

    // ---- epilogue: reduce l, handle all-masked rows, normalize, store ----
#pragma unroll
    for (int mf = 0; mf < 2; mf++) {
#pragma unroll
        for (int h = 0; h < 2; h++) {
            float lt = lrow[mf][h];
            lt += __shfl_xor_sync(0xffffffffu, lt, 1);
            lt += __shfl_xor_sync(0xffffffffu, lt, 2);

            if (lt == 0.0f) {
                // reference: softmax over all-(-max) row = uniform over ALL keys
                for (int j = 0; j < NSEQ; j++) {
                    const float* vp = Vbase + (size_t)j * HD;
#pragma unroll
                    for (int nf = 0; nf < 8; nf++) {
                        const int d = nf * 8 + 2 * tg;
                        o[mf][nf][h*2]   += vp[d];
                        o[mf][nf][h*2+1] += vp[d + 1];
                    }
                }
                lt = (float)NSEQ;
            }
            const float inv = 1.0f / lt;
            const int i0 = qbase + rbase + mf * 16 + g + h * 8;
            float* op = ctx + ((size_t)(b * NSEQ + i0)) * DIM + head * HD;
#pragma unroll
            for (int nf = 0; nf < 8; nf++) {
                float2 v2 = make_float2(o[mf][nf][h*2] * inv, o[mf][nf][h*2+1] * inv);
                *(float2*)(op + nf * 8 + 2 * tg) = v2;
            }
        }
    }
}

// ---------------------------------------------------------------------------
// Zero masked output rows
// ---------------------------------------------------------------------------
__global__ void apply_mask_out(float* __restrict__ out, const void* __restrict__ maskp)
{
    const int mode = g_mask_mode;
    const int idx = blockIdx.x * blockDim.x + threadIdx.x;
    const int total4 = NTOK * (DIM / 4);
    if (idx >= total4) return;
    const int token = idx / (DIM / 4);
    if (!mask_at(maskp, token, mode)) {
        ((float4*)out)[idx] = make_float4(0.f, 0.f, 0.f, 0.f);
    }
}

// ---------------------------------------------------------------------------
// Launcher
// ---------------------------------------------------------------------------
extern "C" void kernel_launch(void* const* d_in, const int* in_sizes, int n_in,
                              void* d_out, int out_size)
{
    const float* x     = (const float*)d_in[0];
    const float* Wqkv  = (const float*)d_in[1];
    const float* Wout  = (const float*)d_in[2];
    const float* qlnw  = (const float*)d_in[3];
    const float* qlnb  = (const float*)d_in[4];
    const float* klnw  = (const float*)d_in[5];
    const float* klnb  = (const float*)d_in[6];
    const float* freqs = (const float*)d_in[7];
    const void*  mask  = d_in[8];
    float* out = (float*)d_out;

    float *qkv, *q, *k, *v, *ctx;
    cudaGetSymbolAddress((void**)&qkv, g_qkv);
    cudaGetSymbolAddress((void**)&q,   g_q);
    cudaGetSymbolAddress((void**)&k,   g_k);
    cudaGetSymbolAddress((void**)&v,   g_v);
    cudaGetSymbolAddress((void**)&ctx, g_ctx);

    const int gemm_smem = 4 * 128 * SSTRIDE * (int)sizeof(float);          // 73728
    const int attn_smem = (2*64*KST + 128*KST + 64) * (int)sizeof(float);  // 69888
    cudaFuncSetAttribute(gemm_nt_tf32,  cudaFuncAttributeMaxDynamicSharedMemorySize, gemm_smem);
    cudaFuncSetAttribute(attn_tc_kernel, cudaFuncAttributeMaxDynamicSharedMemorySize, attn_smem);

    detect_mask_kernel<<<1, 32>>>(mask);

    // qkv = x @ W_qkv^T
    gemm_nt_tf32<<<dim3(QKVN / 128, NTOK / 128), 256, gemm_smem>>>(x, Wqkv, qkv, NTOK, QKVN, DIM);

    // per-head LN + RoPE + relayout
    lnrope_kernel<<<(NTOK * NH) / 4, 128>>>(qkv, qlnw, qlnb, klnw, klnb, freqs, q, k, v);

    // tensor-core attention
    attn_tc_kernel<<<dim3(NSEQ / 128, NBH), 128, attn_smem>>>(q, k, v, mask, ctx);

    // out = ctx @ W_out^T
    gemm_nt_tf32<<<dim3(DIM / 128, NTOK / 128), 256, gemm_smem>>>(ctx, Wout, out, NTOK, DIM, DIM);

    // zero masked rows
    apply_mask_out<<<(NTOK * (DIM / 4) + 255) / 256, 256>>>(out, mask);
}